// round 1
// baseline (speedup 1.0000x reference)
#include <cuda_runtime.h>
#include <cstdint>

#define Bx  4
#define Sx  2048
#define Dx  1024
#define Hx  16
#define DKx 64

// Scratch (device globals: no allocations allowed in kernel_launch)
__device__ float g_Q[(size_t)Bx*Hx*Sx*DKx];
__device__ float g_K[(size_t)Bx*Hx*Sx*DKx];
__device__ float g_V[(size_t)Bx*Hx*Sx*DKx];
__device__ float g_C[(size_t)Bx*Hx*Sx*DKx];

// ---------------------------------------------------------------------------
// GEMM: out = A @ W^T + bias.
// MODE 0: A is [B*S, D] row-major; store remapped to [B,H,S,DK].
// MODE 1: A is ctx in [B,H,S,DK] layout (gather-remapped read); store [B*S, D].
// 64x64 tile, BK=16, 256 threads, 4x4 register tile per thread.
// ---------------------------------------------------------------------------
template<int MODE>
__global__ __launch_bounds__(256)
void gemm_kernel(const float* __restrict__ A, const float* __restrict__ W,
                 const float* __restrict__ bias, float* __restrict__ out)
{
    __shared__ float As[16][66];   // k-major, stride 66: conflict-free STS, 8B-aligned LDS
    __shared__ float Bs[16][66];

    const int tid = threadIdx.x;
    const int tr  = tid >> 4;      // 0..15
    const int tc  = tid & 15;      // 0..15
    const int rbase = blockIdx.x * 64;
    const int cbase = blockIdx.y * 64;

    float acc[4][4];
    #pragma unroll
    for (int i = 0; i < 4; i++)
        #pragma unroll
        for (int j = 0; j < 4; j++) acc[i][j] = 0.f;

    for (int k0 = 0; k0 < Dx; k0 += 16) {
        #pragma unroll
        for (int i = 0; i < 4; i++) {
            int flat = tid + i * 256;         // 0..1023
            int k    = flat & 15;
            int idx  = flat >> 4;             // 0..63
            int row  = rbase + idx;
            float av;
            if (MODE == 0) {
                av = A[(size_t)row * Dx + k0 + k];
            } else {
                int kk2 = k0 + k;
                int bb = row >> 11, ss = row & (Sx - 1);
                int hh = kk2 >> 6,  dd = kk2 & 63;
                av = A[(((size_t)bb * Hx + hh) * Sx + ss) * DKx + dd];
            }
            As[k][idx] = av;
            int col = cbase + idx;
            Bs[k][idx] = W[(size_t)col * Dx + k0 + k];
        }
        __syncthreads();

        #pragma unroll
        for (int kk = 0; kk < 16; kk++) {
            float2 a01 = *(const float2*)&As[kk][tr * 4];
            float2 a23 = *(const float2*)&As[kk][tr * 4 + 2];
            float2 b01 = *(const float2*)&Bs[kk][tc * 4];
            float2 b23 = *(const float2*)&Bs[kk][tc * 4 + 2];
            float a[4] = {a01.x, a01.y, a23.x, a23.y};
            float b[4] = {b01.x, b01.y, b23.x, b23.y};
            #pragma unroll
            for (int i = 0; i < 4; i++)
                #pragma unroll
                for (int j = 0; j < 4; j++)
                    acc[i][j] += a[i] * b[j];
        }
        __syncthreads();
    }

    #pragma unroll
    for (int i = 0; i < 4; i++) {
        int row = rbase + tr * 4 + i;
        #pragma unroll
        for (int j = 0; j < 4; j++) {
            int col = cbase + tc * 4 + j;
            float v = acc[i][j] + bias[col];
            if (MODE == 0) {
                int bb = row >> 11, ss = row & (Sx - 1);
                int hh = col >> 6,  dd = col & 63;
                out[(((size_t)bb * Hx + hh) * Sx + ss) * DKx + dd] = v;
            } else {
                out[(size_t)row * Dx + col] = v;
            }
        }
    }
}

// ---------------------------------------------------------------------------
// Fused flash attention per (b,h, 64-query tile). k-tile = 32.
// Thread grid 16x16: rows r0 = tr*4 (4 rows), score cols tc*2, out cols tc*4.
// Row stats reduced over the 16 threads sharing tr via shfl_xor (lanes mix
// only within the low 4 bits, which is exactly the tc dimension).
// ---------------------------------------------------------------------------
__global__ __launch_bounds__(256)
void attn_kernel(const int* __restrict__ mask, float* __restrict__ ctx)
{
    __shared__ float Qs[64][66];   // [d][r]
    __shared__ float Ks[64][34];   // [d][c]
    __shared__ float Vs[32][64];   // [j][d]
    __shared__ float Ps[32][66];   // [j][r]

    const int tid  = threadIdx.x;
    const int tr   = tid >> 4;
    const int tc   = tid & 15;
    const int bh   = blockIdx.y;
    const int bidx = bh >> 4;             // batch
    const int qbase = blockIdx.x * 64;

    const float* Qg = g_Q + (size_t)bh * Sx * DKx;
    const float* Kg = g_K + (size_t)bh * Sx * DKx;
    const float* Vg = g_V + (size_t)bh * Sx * DKx;
    const int* mrow = mask + ((size_t)bidx * Sx + qbase) * Sx;

    #pragma unroll
    for (int i = 0; i < 16; i++) {
        int flat = tid + i * 256;
        int d = flat & 63, r = flat >> 6;
        Qs[d][r] = Qg[(size_t)(qbase + r) * DKx + d];
    }

    float m_run[4], l_run[4], O[4][4];
    #pragma unroll
    for (int i = 0; i < 4; i++) {
        m_run[i] = -1e30f; l_run[i] = 0.f;
        #pragma unroll
        for (int j = 0; j < 4; j++) O[i][j] = 0.f;
    }
    __syncthreads();

    for (int kb = 0; kb < Sx; kb += 32) {
        #pragma unroll
        for (int i = 0; i < 8; i++) {
            int flat = tid + i * 256;
            int d = flat & 63, c = flat >> 6;
            Ks[d][c] = Kg[(size_t)(kb + c) * DKx + d];
            Vs[c][d] = Vg[(size_t)(kb + c) * DKx + d];
        }
        __syncthreads();

        float s[4][2] = {{0.f,0.f},{0.f,0.f},{0.f,0.f},{0.f,0.f}};
        #pragma unroll 16
        for (int d = 0; d < 64; d++) {
            float2 a01 = *(const float2*)&Qs[d][tr * 4];
            float2 a23 = *(const float2*)&Qs[d][tr * 4 + 2];
            float2 bb  = *(const float2*)&Ks[d][tc * 2];
            s[0][0] += a01.x * bb.x;  s[0][1] += a01.x * bb.y;
            s[1][0] += a01.y * bb.x;  s[1][1] += a01.y * bb.y;
            s[2][0] += a23.x * bb.x;  s[2][1] += a23.x * bb.y;
            s[3][0] += a23.y * bb.x;  s[3][1] += a23.y * bb.y;
        }

        // scale + mask
        #pragma unroll
        for (int ri = 0; ri < 4; ri++) {
            int r = tr * 4 + ri;
            #pragma unroll
            for (int cj = 0; cj < 2; cj++) {
                int kc = kb + tc * 2 + cj;
                int mv = mrow[(size_t)r * Sx + kc];
                s[ri][cj] = (mv == 0) ? -1e9f : s[ri][cj] * 0.125f;
            }
        }

        // online softmax update (row stats across the 16 tc-threads)
        #pragma unroll
        for (int ri = 0; ri < 4; ri++) {
            float mt = fmaxf(s[ri][0], s[ri][1]);
            #pragma unroll
            for (int off = 1; off < 16; off <<= 1)
                mt = fmaxf(mt, __shfl_xor_sync(0xffffffffu, mt, off));
            float m_new = fmaxf(m_run[ri], mt);
            float scale = __expf(m_run[ri] - m_new);
            m_run[ri] = m_new;
            float p0 = __expf(s[ri][0] - m_new);
            float p1 = __expf(s[ri][1] - m_new);
            float ps = p0 + p1;
            #pragma unroll
            for (int off = 1; off < 16; off <<= 1)
                ps += __shfl_xor_sync(0xffffffffu, ps, off);
            l_run[ri] = l_run[ri] * scale + ps;
            #pragma unroll
            for (int j = 0; j < 4; j++) O[ri][j] *= scale;
            Ps[tc * 2 + 0][tr * 4 + ri] = p0;
            Ps[tc * 2 + 1][tr * 4 + ri] = p1;
        }
        __syncthreads();

        // O += P @ V
        #pragma unroll 8
        for (int j = 0; j < 32; j++) {
            float2 p01 = *(const float2*)&Ps[j][tr * 4];
            float2 p23 = *(const float2*)&Ps[j][tr * 4 + 2];
            float4 vv  = *(const float4*)&Vs[j][tc * 4];
            float p[4] = {p01.x, p01.y, p23.x, p23.y};
            #pragma unroll
            for (int i = 0; i < 4; i++) {
                O[i][0] += p[i] * vv.x;
                O[i][1] += p[i] * vv.y;
                O[i][2] += p[i] * vv.z;
                O[i][3] += p[i] * vv.w;
            }
        }
        __syncthreads();
    }

    #pragma unroll
    for (int ri = 0; ri < 4; ri++) {
        float inv = 1.0f / l_run[ri];
        int r = qbase + tr * 4 + ri;
        #pragma unroll
        for (int j = 0; j < 4; j++)
            ctx[((size_t)bh * Sx + r) * DKx + tc * 4 + j] = O[ri][j] * inv;
    }
}

// ---------------------------------------------------------------------------
extern "C" void kernel_launch(void* const* d_in, const int* in_sizes, int n_in,
                              void* d_out, int out_size)
{
    const float* query = (const float*)d_in[0];
    const float* key   = (const float*)d_in[1];
    const float* value = (const float*)d_in[2];
    const int*   mask  = (const int*)d_in[3];
    const float* Wq = (const float*)d_in[4];
    const float* bq = (const float*)d_in[5];
    const float* Wk = (const float*)d_in[6];
    const float* bk = (const float*)d_in[7];
    const float* Wv = (const float*)d_in[8];
    const float* bv = (const float*)d_in[9];
    const float* Wo = (const float*)d_in[10];
    const float* bo = (const float*)d_in[11];
    float* out = (float*)d_out;

    float *Qb, *Kb, *Vb, *Cb;
    cudaGetSymbolAddress((void**)&Qb, g_Q);
    cudaGetSymbolAddress((void**)&Kb, g_K);
    cudaGetSymbolAddress((void**)&Vb, g_V);
    cudaGetSymbolAddress((void**)&Cb, g_C);

    dim3 blk(256);
    dim3 gproj((Bx * Sx) / 64, Dx / 64);   // 128 x 16

    gemm_kernel<0><<<gproj, blk>>>(query, Wq, bq, Qb);
    gemm_kernel<0><<<gproj, blk>>>(key,   Wk, bk, Kb);
    gemm_kernel<0><<<gproj, blk>>>(value, Wv, bv, Vb);
    attn_kernel<<<dim3(Sx / 64, Bx * Hx), blk>>>(mask, Cb);
    gemm_kernel<1><<<gproj, blk>>>(Cb, Wo, bo, out);
}

// round 3
// speedup vs baseline: 4.2012x; 4.2012x over previous
#include <cuda_runtime.h>
#include <cstdint>

#define Bx 4
#define Sx 2048
#define Dx 1024
#define Hx 16
#define DKx 64
#define SW 36      // gemm smem stride (floats)
#define AW 68      // attn smem stride (floats)

__device__ float g_Q[(size_t)Bx*Hx*Sx*DKx];
__device__ float g_K[(size_t)Bx*Hx*Sx*DKx];
__device__ float g_Vt[(size_t)Bx*Hx*Sx*DKx];   // [B,H,DK,S]
__device__ float g_C[(size_t)Bx*Hx*Sx*DKx];
__device__ unsigned g_mb[(size_t)Bx*Sx*(Sx/32)];

__device__ __forceinline__ uint32_t f2tf(float x) {
    uint32_t r; asm("cvt.rna.tf32.f32 %0, %1;" : "=r"(r) : "f"(x)); return r;
}
__device__ __forceinline__ void mma8(float* d, const uint32_t* a, const uint32_t* b) {
    asm volatile("mma.sync.aligned.m16n8k8.row.col.f32.tf32.tf32.f32 "
        "{%0,%1,%2,%3}, {%4,%5,%6,%7}, {%8,%9}, {%0,%1,%2,%3};"
        : "+f"(d[0]), "+f"(d[1]), "+f"(d[2]), "+f"(d[3])
        : "r"(a[0]), "r"(a[1]), "r"(a[2]), "r"(a[3]), "r"(b[0]), "r"(b[1]));
}
__device__ __forceinline__ void cp16(float* s, const float* g) {
    uint32_t sa = (uint32_t)__cvta_generic_to_shared(s);
    asm volatile("cp.async.cg.shared.global [%0], [%1], 16;" :: "r"(sa), "l"(g));
}
__device__ __forceinline__ void cp8(void* s, const void* g) {
    uint32_t sa = (uint32_t)__cvta_generic_to_shared(s);
    asm volatile("cp.async.ca.shared.global [%0], [%1], 8;" :: "r"(sa), "l"(g));
}
#define CP_COMMIT() asm volatile("cp.async.commit_group;")
#define CP_WAIT(N)  asm volatile("cp.async.wait_group %0;" :: "n"(N))

// ---------------------------------------------------------------------------
// Pack mask [B,S,S] int32 -> bitfield (1 bit per element)
// ---------------------------------------------------------------------------
__global__ void pack_mask(const int* __restrict__ mask, unsigned* __restrict__ mb)
{
    size_t i = (size_t)blockIdx.x * blockDim.x + threadIdx.x;
    int v = mask[i] != 0;
    unsigned bits = __ballot_sync(0xffffffffu, v);
    if ((threadIdx.x & 31) == 0) mb[i >> 5] = bits;
}

// ---------------------------------------------------------------------------
// tf32 GEMM: out = A @ W^T + bias.  CTA 128x128, BK=32, 256 thr, warp 64x32.
// MODE 0: A [B*S,D] row-major, store remap to [B,H,S,DK]
// MODE 1: A gathered from [B,H,S,DK], store [B*S,D]
// MODE 2: A [B*S,D] row-major, store remap to [B,H,DK,S] (transposed V)
// ---------------------------------------------------------------------------
template<int MODE>
__global__ __launch_bounds__(256, 2)
void gemm_tf32(const float* __restrict__ A, const float* __restrict__ W,
               const float* __restrict__ bias, float* __restrict__ out)
{
    extern __shared__ float sm[];
    float* As = sm;                 // [2][128][SW]
    float* Bs = sm + 2*128*SW;      // [2][128][SW]

    const int tid  = threadIdx.x;
    const int lane = tid & 31;
    const int w    = tid >> 5;
    const int wm   = (w >> 2) * 64;
    const int wn   = (w & 3) * 32;
    const int rbase = blockIdx.x * 128;
    const int cbase = blockIdx.y * 128;
    const int lr = lane >> 2, lc = lane & 3;

    float acc[4][4][4];
    #pragma unroll
    for (int i = 0; i < 4; i++)
        #pragma unroll
        for (int j = 0; j < 4; j++)
            #pragma unroll
            for (int k = 0; k < 4; k++) acc[i][j][k] = 0.f;

    auto load_stage = [&](int st, int k0) {
        #pragma unroll
        for (int i = 0; i < 4; i++) {
            int q = tid + i * 256;
            int row = q >> 3, cq = (q & 7) * 4;
            const float* srcA;
            if (MODE == 1) {
                int gr = rbase + row, k = k0 + cq;
                srcA = A + (((size_t)(gr >> 11) * Hx + (k >> 6)) * Sx + (gr & (Sx-1))) * DKx + (k & 63);
            } else {
                srcA = A + (size_t)(rbase + row) * Dx + k0 + cq;
            }
            cp16(As + ((size_t)st * 128 + row) * SW + cq, srcA);
            cp16(Bs + ((size_t)st * 128 + row) * SW + cq,
                 W + (size_t)(cbase + row) * Dx + k0 + cq);
        }
        CP_COMMIT();
    };

    load_stage(0, 0);
    const int NIT = Dx / 32;
    for (int it = 0; it < NIT; it++) {
        if (it + 1 < NIT) { load_stage((it + 1) & 1, (it + 1) * 32); CP_WAIT(1); }
        else              { CP_WAIT(0); }
        __syncthreads();
        const float* a   = As + (size_t)(it & 1) * 128 * SW;
        const float* bsh = Bs + (size_t)(it & 1) * 128 * SW;
        #pragma unroll
        for (int ks = 0; ks < 4; ks++) {
            const int kk = ks * 8 + lc;
            uint32_t af[4][4], bf[4][2];
            #pragma unroll
            for (int mt = 0; mt < 4; mt++) {
                const float* p = a + (wm + mt * 16 + lr) * SW + kk;
                af[mt][0] = f2tf(p[0]);
                af[mt][1] = f2tf(p[8 * SW]);
                af[mt][2] = f2tf(p[4]);
                af[mt][3] = f2tf(p[8 * SW + 4]);
            }
            #pragma unroll
            for (int nt = 0; nt < 4; nt++) {
                const float* p = bsh + (wn + nt * 8 + lr) * SW + kk;
                bf[nt][0] = f2tf(p[0]);
                bf[nt][1] = f2tf(p[4]);
            }
            #pragma unroll
            for (int mt = 0; mt < 4; mt++)
                #pragma unroll
                for (int nt = 0; nt < 4; nt++)
                    mma8(acc[mt][nt], af[mt], bf[nt]);
        }
        __syncthreads();
    }

    #pragma unroll
    for (int mt = 0; mt < 4; mt++) {
        int row = rbase + wm + mt * 16 + lr;
        #pragma unroll
        for (int nt = 0; nt < 4; nt++) {
            int col = cbase + wn + nt * 8 + 2 * lc;
            float b0 = bias[col], b1 = bias[col + 1];
            float v0 = acc[mt][nt][0] + b0, v1 = acc[mt][nt][1] + b1;
            float v2 = acc[mt][nt][2] + b0, v3 = acc[mt][nt][3] + b1;
            if (MODE == 0) {
                int bb = row >> 11, ss = row & (Sx - 1);
                int hh = col >> 6,  dd = col & 63;
                size_t base = ((size_t)bb * Hx + hh) * Sx;
                *(float2*)&out[(base + ss) * DKx + dd]     = make_float2(v0, v1);
                *(float2*)&out[(base + ss + 8) * DKx + dd] = make_float2(v2, v3);
            } else if (MODE == 1) {
                *(float2*)&out[(size_t)row * Dx + col]       = make_float2(v0, v1);
                *(float2*)&out[(size_t)(row + 8) * Dx + col] = make_float2(v2, v3);
            } else {
                int bb = row >> 11, ss = row & (Sx - 1);
                int hh = col >> 6,  dd = col & 63;
                size_t base = ((size_t)bb * Hx + hh) * DKx;
                out[(base + dd)     * Sx + ss]     = v0;
                out[(base + dd + 1) * Sx + ss]     = v1;
                out[(base + dd)     * Sx + ss + 8] = v2;
                out[(base + dd + 1) * Sx + ss + 8] = v3;
            }
        }
    }
}

// ---------------------------------------------------------------------------
// Fused flash attention, tf32 tensor cores.
// q-tile 256 (8 warps x 32 rows), k-tile 64, double-buffered K/V/mask.
// ---------------------------------------------------------------------------
__global__ __launch_bounds__(256, 1)
void attn_tf32(float* __restrict__ ctx)
{
    extern __shared__ float sm[];
    float* Qs = sm;                              // 256*AW
    float* Ks = Qs + 256 * AW;                   // [2][64*AW]
    float* Vs = Ks + 2 * 64 * AW;                // [2][64*AW]
    float* Ps = Vs + 2 * 64 * AW;                // 256*AW
    unsigned* MB = (unsigned*)(Ps + 256 * AW);   // [2][512]

    const int tid = threadIdx.x, lane = tid & 31, w = tid >> 5;
    const int lr = lane >> 2, lc = lane & 3;
    const int bh = blockIdx.z * Hx + blockIdx.x;
    const int qbase = blockIdx.y * 256;
    const float* Qg = g_Q  + (size_t)bh * Sx * DKx;
    const float* Kg = g_K  + (size_t)bh * Sx * DKx;
    const float* Vg = g_Vt + (size_t)bh * Sx * DKx;   // [d][s]
    const unsigned* mbg = g_mb + ((size_t)blockIdx.z * Sx + qbase) * (Sx / 32);

    // Q tile -> smem (joins stage-0 cp.async group)
    #pragma unroll
    for (int i = 0; i < 16; i++) {
        int q = tid + i * 256;
        int row = q >> 4, cq = (q & 15) * 4;
        cp16(Qs + row * AW + cq, Qg + (size_t)(qbase + row) * DKx + cq);
    }

    auto load_kv = [&](int st, int kb) {
        #pragma unroll
        for (int i = 0; i < 4; i++) {
            int q = tid + i * 256;
            int row = q >> 4, cq = (q & 15) * 4;
            cp16(Ks + (st * 64 + row) * AW + cq, Kg + (size_t)(kb + row) * DKx + cq);
            cp16(Vs + (st * 64 + row) * AW + cq, Vg + (size_t)row * Sx + kb + cq);
        }
        cp8(MB + st * 512 + tid * 2, mbg + (size_t)tid * (Sx / 32) + (kb >> 5));
        CP_COMMIT();
    };
    load_kv(0, 0);

    float O[2][8][4];
    #pragma unroll
    for (int i = 0; i < 2; i++)
        #pragma unroll
        for (int j = 0; j < 8; j++)
            #pragma unroll
            for (int k = 0; k < 4; k++) O[i][j][k] = 0.f;
    float mrun[4] = {-1e30f, -1e30f, -1e30f, -1e30f};
    float lrun[4] = {0.f, 0.f, 0.f, 0.f};

    const int NIT = Sx / 64;
    for (int it = 0; it < NIT; it++) {
        if (it + 1 < NIT) { load_kv((it + 1) & 1, (it + 1) * 64); CP_WAIT(1); }
        else              { CP_WAIT(0); }
        __syncthreads();
        const float* ks_ = Ks + (it & 1) * 64 * AW;
        const float* vs_ = Vs + (it & 1) * 64 * AW;
        const unsigned* mb_ = MB + (it & 1) * 512;

        // ---- scores S = Q K^T ----
        float S[2][8][4];
        #pragma unroll
        for (int i = 0; i < 2; i++)
            #pragma unroll
            for (int j = 0; j < 8; j++)
                #pragma unroll
                for (int k = 0; k < 4; k++) S[i][j][k] = 0.f;

        #pragma unroll
        for (int ks = 0; ks < 8; ks++) {
            const int kk = ks * 8 + lc;
            uint32_t qf[2][4], kf[8][2];
            #pragma unroll
            for (int mt = 0; mt < 2; mt++) {
                const float* p = Qs + (w * 32 + mt * 16 + lr) * AW + kk;
                qf[mt][0] = f2tf(p[0]);
                qf[mt][1] = f2tf(p[8 * AW]);
                qf[mt][2] = f2tf(p[4]);
                qf[mt][3] = f2tf(p[8 * AW + 4]);
            }
            #pragma unroll
            for (int nt = 0; nt < 8; nt++) {
                const float* p = ks_ + (nt * 8 + lr) * AW + kk;
                kf[nt][0] = f2tf(p[0]);
                kf[nt][1] = f2tf(p[4]);
            }
            #pragma unroll
            for (int mt = 0; mt < 2; mt++)
                #pragma unroll
                for (int nt = 0; nt < 8; nt++)
                    mma8(S[mt][nt], qf[mt], kf[nt]);
        }

        // ---- mask + online softmax + P -> smem ----
        #pragma unroll
        for (int mt = 0; mt < 2; mt++) {
            const int rl = w * 32 + mt * 16 + lr;
            const unsigned m0a = mb_[rl * 2],       m0b = mb_[rl * 2 + 1];
            const unsigned m1a = mb_[(rl + 8) * 2], m1b = mb_[(rl + 8) * 2 + 1];
            #pragma unroll
            for (int nt = 0; nt < 8; nt++) {
                const int sh = (nt * 8 + 2 * lc) & 31;
                const unsigned wa = (nt < 4) ? m0a : m0b;
                const unsigned wb = (nt < 4) ? m1a : m1b;
                S[mt][nt][0] = ((wa >> sh) & 1)       ? S[mt][nt][0] * 0.125f : -1e9f;
                S[mt][nt][1] = ((wa >> (sh + 1)) & 1) ? S[mt][nt][1] * 0.125f : -1e9f;
                S[mt][nt][2] = ((wb >> sh) & 1)       ? S[mt][nt][2] * 0.125f : -1e9f;
                S[mt][nt][3] = ((wb >> (sh + 1)) & 1) ? S[mt][nt][3] * 0.125f : -1e9f;
            }
            #pragma unroll
            for (int hf = 0; hf < 2; hf++) {
                const int idx = mt * 2 + hf;
                float mx = -1e30f;
                #pragma unroll
                for (int nt = 0; nt < 8; nt++)
                    mx = fmaxf(mx, fmaxf(S[mt][nt][2 * hf], S[mt][nt][2 * hf + 1]));
                mx = fmaxf(mx, __shfl_xor_sync(0xffffffffu, mx, 1));
                mx = fmaxf(mx, __shfl_xor_sync(0xffffffffu, mx, 2));
                const float mnew = fmaxf(mrun[idx], mx);
                const float scl = __expf(mrun[idx] - mnew);
                mrun[idx] = mnew;
                float rs = 0.f;
                #pragma unroll
                for (int nt = 0; nt < 8; nt++) {
                    float p0 = __expf(S[mt][nt][2 * hf]     - mnew);
                    float p1 = __expf(S[mt][nt][2 * hf + 1] - mnew);
                    S[mt][nt][2 * hf] = p0; S[mt][nt][2 * hf + 1] = p1;
                    rs += p0 + p1;
                }
                rs += __shfl_xor_sync(0xffffffffu, rs, 1);
                rs += __shfl_xor_sync(0xffffffffu, rs, 2);
                lrun[idx] = lrun[idx] * scl + rs;
                #pragma unroll
                for (int nd = 0; nd < 8; nd++) {
                    O[mt][nd][2 * hf]     *= scl;
                    O[mt][nd][2 * hf + 1] *= scl;
                }
                const int rr = rl + hf * 8;
                #pragma unroll
                for (int nt = 0; nt < 8; nt++)
                    *(float2*)&Ps[rr * AW + nt * 8 + 2 * lc] =
                        make_float2(S[mt][nt][2 * hf], S[mt][nt][2 * hf + 1]);
            }
        }
        __syncwarp();   // Ps rows are warp-private

        // ---- O += P @ V ----
        #pragma unroll
        for (int ks = 0; ks < 8; ks++) {
            const int kk = ks * 8 + lc;
            uint32_t pf[2][4], vf[8][2];
            #pragma unroll
            for (int mt = 0; mt < 2; mt++) {
                const float* p = Ps + (w * 32 + mt * 16 + lr) * AW + kk;
                pf[mt][0] = f2tf(p[0]);
                pf[mt][1] = f2tf(p[8 * AW]);
                pf[mt][2] = f2tf(p[4]);
                pf[mt][3] = f2tf(p[8 * AW + 4]);
            }
            #pragma unroll
            for (int nt = 0; nt < 8; nt++) {
                const float* p = vs_ + (nt * 8 + lr) * AW + kk;
                vf[nt][0] = f2tf(p[0]);
                vf[nt][1] = f2tf(p[4]);
            }
            #pragma unroll
            for (int mt = 0; mt < 2; mt++)
                #pragma unroll
                for (int nt = 0; nt < 8; nt++)
                    mma8(O[mt][nt], pf[mt], vf[nt]);
        }
        __syncthreads();
    }

    #pragma unroll
    for (int mt = 0; mt < 2; mt++)
        #pragma unroll
        for (int hf = 0; hf < 2; hf++) {
            const float inv = 1.f / lrun[mt * 2 + hf];
            const int row = qbase + w * 32 + mt * 16 + lr + hf * 8;
            float* dst = ctx + ((size_t)bh * Sx + row) * DKx;
            #pragma unroll
            for (int nd = 0; nd < 8; nd++)
                *(float2*)&dst[nd * 8 + 2 * lc] =
                    make_float2(O[mt][nd][2 * hf] * inv, O[mt][nd][2 * hf + 1] * inv);
        }
}

// ---------------------------------------------------------------------------
extern "C" void kernel_launch(void* const* d_in, const int* in_sizes, int n_in,
                              void* d_out, int out_size)
{
    const float* query = (const float*)d_in[0];
    const float* key   = (const float*)d_in[1];
    const float* value = (const float*)d_in[2];
    const int*   mask  = (const int*)d_in[3];
    const float* Wq = (const float*)d_in[4];
    const float* bq = (const float*)d_in[5];
    const float* Wk = (const float*)d_in[6];
    const float* bk = (const float*)d_in[7];
    const float* Wv = (const float*)d_in[8];
    const float* bv = (const float*)d_in[9];
    const float* Wo = (const float*)d_in[10];
    const float* bo = (const float*)d_in[11];
    float* out = (float*)d_out;

    float *Qb, *Kb, *Vb, *Cb; unsigned* Mb;
    cudaGetSymbolAddress((void**)&Qb, g_Q);
    cudaGetSymbolAddress((void**)&Kb, g_K);
    cudaGetSymbolAddress((void**)&Vb, g_Vt);
    cudaGetSymbolAddress((void**)&Cb, g_C);
    cudaGetSymbolAddress((void**)&Mb, g_mb);

    static bool attr_done = false;
    if (!attr_done) {
        cudaFuncSetAttribute(gemm_tf32<0>, cudaFuncAttributeMaxDynamicSharedMemorySize, 73728);
        cudaFuncSetAttribute(gemm_tf32<1>, cudaFuncAttributeMaxDynamicSharedMemorySize, 73728);
        cudaFuncSetAttribute(gemm_tf32<2>, cudaFuncAttributeMaxDynamicSharedMemorySize, 73728);
        cudaFuncSetAttribute(attn_tf32,    cudaFuncAttributeMaxDynamicSharedMemorySize, 212992);
        attr_done = true;
    }

    dim3 blk(256);
    dim3 gproj(64, 8);                    // 8192/128 x 1024/128

    pack_mask<<<65536, 256>>>(mask, Mb);
    gemm_tf32<0><<<gproj, blk, 73728>>>(query, Wq, bq, Qb);
    gemm_tf32<0><<<gproj, blk, 73728>>>(key,   Wk, bk, Kb);
    gemm_tf32<2><<<gproj, blk, 73728>>>(value, Wv, bv, Vb);
    attn_tf32<<<dim3(Hx, Sx / 256, Bx), blk, 212992>>>(Cb);
    gemm_tf32<1><<<gproj, blk, 73728>>>(Cb, Wo, bo, out);
}